// round 12
// baseline (speedup 1.0000x reference)
#include <cuda_runtime.h>
#include <cuda_bf16.h>
#include <cstdint>

#define NN 100000
#define EE 1600000
#define NBLK ((NN + 1023) / 1024)   // 98
#define WTOT 147456                  // total weight elements across 6 matrices

typedef __nv_bfloat16 bf16;

// ---------------- scratch (device globals; no allocation) ----------------
__device__ int      g_is64;
__device__ int      g_deg[NN];
__device__ int      g_off[NN + 1];
__device__ int      g_cursor[NN];
__device__ int      g_bsum[128];
__device__ unsigned g_tick;
__device__ int      g_csr[EE];
__device__ float    g_buf[(size_t)NN * 256];  // mean1 -> pq -> hid (reused)
__device__ float    g_h[(size_t)NN * 256];    // hidden after layer 1
__device__ float    g_gr[(size_t)NN * 256];   // Gr = x @ W_r1^T + b_l1 (side stream)
__device__ float    g_bias2[128];             // [0(64) | b_l2(64)]
__device__ bf16     g_whi[WTOT], g_wlo[WTOT];

__device__ __forceinline__ int OFF(int i) { return g_off[i] + g_bsum[i >> 10]; }

// ---------------- prep: split weights + zero + dtype detect ----------------
__global__ void k_prep(const unsigned* ei,
                       const float* Wl1, const float* Wr1,
                       const float* Wl2, const float* Wr2,
                       const float* fc1, const float* fc2,
                       const float* bl2) {
    int i = blockIdx.x * blockDim.x + threadIdx.x;
    if (i == 0) {
        int is64 = 1;
        for (int t = 0; t < 1024; t++)
            if (ei[2 * t + 1] != 0u) { is64 = 0; break; }
        g_is64 = is64;
        g_tick = 0u;
    }
    if (i < NN) { g_deg[i] = 0; g_cursor[i] = 0; }
    if (i < 128) g_bias2[i] = (i < 64) ? 0.f : bl2[i - 64];
    if (i < WTOT) {
        const float* src; int off;
        if      (i < 32768)  { src = Wl1; off = 0; }
        else if (i < 65536)  { src = Wr1; off = 32768; }
        else if (i < 81920)  { src = Wl2; off = 65536; }
        else if (i < 98304)  { src = Wr2; off = 81920; }
        else if (i < 114688) { src = fc1; off = 98304; }
        else                 { src = fc2; off = 114688; }
        float a = src[i - off];
        bf16 h = __float2bfloat16(a);
        g_whi[i] = h;
        g_wlo[i] = __float2bfloat16(a - __bfloat162float(h));
    }
}

__device__ __forceinline__ int eidx(const void* ei, int is64, int idx) {
    if (is64) return (int)((const long long*)ei)[idx];
    return ((const int*)ei)[idx];
}

// 2 edges per thread, vector loads of the dst halves
__global__ void k_hist(const void* ei) {
    int t = blockIdx.x * blockDim.x + threadIdx.x;
    int e = t * 2;
    if (e >= EE) return;
    if (g_is64) {
        longlong2 d = __ldg((const longlong2*)((const long long*)ei + EE) + t);
        atomicAdd(&g_deg[(int)d.x], 1);
        atomicAdd(&g_deg[(int)d.y], 1);
    } else {
        int2 d = __ldg((const int2*)((const int*)ei + EE) + t);
        atomicAdd(&g_deg[d.x], 1);
        atomicAdd(&g_deg[d.y], 1);
    }
}

// ---- fused scan: per-block local scan + decoupled last-block base scan ----
__global__ void k_scan() {
    __shared__ int ws[32];
    __shared__ unsigned last;
    int tid = threadIdx.x, lane = tid & 31, warp = tid >> 5;
    int i = blockIdx.x * 1024 + tid;
    int v = (i < NN) ? g_deg[i] : 0;
    int x = v;
    #pragma unroll
    for (int o = 1; o < 32; o <<= 1) {
        int y = __shfl_up_sync(0xFFFFFFFFu, x, o);
        if (lane >= o) x += y;
    }
    if (lane == 31) ws[warp] = x;
    __syncthreads();
    if (tid < 32) {
        int s = ws[tid];
        #pragma unroll
        for (int o = 1; o < 32; o <<= 1) {
            int y = __shfl_up_sync(0xFFFFFFFFu, s, o);
            if (tid >= o) s += y;
        }
        ws[tid] = s;
    }
    __syncthreads();
    int excl = (warp ? ws[warp - 1] : 0) + (x - v);
    if (i <= NN) g_off[i] = excl;
    if (tid == 0) g_bsum[blockIdx.x] = ws[31];
    __threadfence();
    __syncthreads();
    if (tid == 0) last = (atomicAdd(&g_tick, 1u) == (unsigned)(NBLK - 1)) ? 1u : 0u;
    __syncthreads();
    if (last && tid < 128) {
        int t = tid, ln = t & 31, wp = t >> 5;
        int bv = (t < NBLK) ? *(volatile int*)&g_bsum[t] : 0;
        int bx = bv;
        #pragma unroll
        for (int o = 1; o < 32; o <<= 1) {
            int y = __shfl_up_sync(0xFFFFFFFFu, bx, o);
            if (ln >= o) bx += y;
        }
        if (ln == 31) ws[wp] = bx;
        __syncwarp();
        if (t == 0) { int a = ws[0]; ws[4] = 0; ws[5] = a; ws[6] = a + ws[1]; ws[7] = a + ws[1] + ws[2]; }
        __syncthreads();
        if (t < NBLK) g_bsum[t] = ws[4 + wp] + bx - bv;
    }
}

// 2 edges per thread, vectorized
__global__ void k_scatter(const void* ei) {
    int t = blockIdx.x * blockDim.x + threadIdx.x;
    int e = t * 2;
    if (e >= EE) return;
    if (g_is64) {
        longlong2 s = __ldg((const longlong2*)((const long long*)ei) + t);
        longlong2 d = __ldg((const longlong2*)((const long long*)ei + EE) + t);
        int p0 = atomicAdd(&g_cursor[(int)d.x], 1);
        g_csr[OFF((int)d.x) + p0] = (int)s.x;
        int p1 = atomicAdd(&g_cursor[(int)d.y], 1);
        g_csr[OFF((int)d.y) + p1] = (int)s.y;
    } else {
        int2 s = __ldg((const int2*)((const int*)ei) + t);
        int2 d = __ldg((const int2*)((const int*)ei + EE) + t);
        int p0 = atomicAdd(&g_cursor[d.x], 1);
        g_csr[OFF(d.x) + p0] = s.x;
        int p1 = atomicAdd(&g_cursor[d.y], 1);
        g_csr[OFF(d.y) + p1] = s.y;
    }
}

// ---------------- mean aggregation (F=128): warp/node, 8-way MLP ----------
__global__ void k_agg128(const float* __restrict__ X, float* __restrict__ out) {
    int gw = (blockIdx.x * blockDim.x + threadIdx.x) >> 5;
    int lane = threadIdx.x & 31;
    if (gw >= NN) return;
    int beg = OFF(gw), end = OFF(gw + 1);
    float4 a0 = make_float4(0.f, 0.f, 0.f, 0.f);
    float4 a1 = a0, a2 = a0, a3 = a0, a4 = a0, a5 = a0, a6 = a0, a7 = a0;
    const float4* base = (const float4*)X;
    int e = beg;
    for (; e + 8 <= end; e += 8) {
        int s0 = g_csr[e],     s1 = g_csr[e + 1], s2 = g_csr[e + 2], s3 = g_csr[e + 3];
        int s4 = g_csr[e + 4], s5 = g_csr[e + 5], s6 = g_csr[e + 6], s7 = g_csr[e + 7];
        float4 v0 = __ldg(base + (size_t)s0 * 32 + lane);
        float4 v1 = __ldg(base + (size_t)s1 * 32 + lane);
        float4 v2 = __ldg(base + (size_t)s2 * 32 + lane);
        float4 v3 = __ldg(base + (size_t)s3 * 32 + lane);
        float4 v4 = __ldg(base + (size_t)s4 * 32 + lane);
        float4 v5 = __ldg(base + (size_t)s5 * 32 + lane);
        float4 v6 = __ldg(base + (size_t)s6 * 32 + lane);
        float4 v7 = __ldg(base + (size_t)s7 * 32 + lane);
        a0.x += v0.x; a0.y += v0.y; a0.z += v0.z; a0.w += v0.w;
        a1.x += v1.x; a1.y += v1.y; a1.z += v1.z; a1.w += v1.w;
        a2.x += v2.x; a2.y += v2.y; a2.z += v2.z; a2.w += v2.w;
        a3.x += v3.x; a3.y += v3.y; a3.z += v3.z; a3.w += v3.w;
        a4.x += v4.x; a4.y += v4.y; a4.z += v4.z; a4.w += v4.w;
        a5.x += v5.x; a5.y += v5.y; a5.z += v5.z; a5.w += v5.w;
        a6.x += v6.x; a6.y += v6.y; a6.z += v6.z; a6.w += v6.w;
        a7.x += v7.x; a7.y += v7.y; a7.z += v7.z; a7.w += v7.w;
    }
    for (; e + 4 <= end; e += 4) {
        int s0 = g_csr[e], s1 = g_csr[e + 1], s2 = g_csr[e + 2], s3 = g_csr[e + 3];
        float4 v0 = __ldg(base + (size_t)s0 * 32 + lane);
        float4 v1 = __ldg(base + (size_t)s1 * 32 + lane);
        float4 v2 = __ldg(base + (size_t)s2 * 32 + lane);
        float4 v3 = __ldg(base + (size_t)s3 * 32 + lane);
        a0.x += v0.x; a0.y += v0.y; a0.z += v0.z; a0.w += v0.w;
        a1.x += v1.x; a1.y += v1.y; a1.z += v1.z; a1.w += v1.w;
        a2.x += v2.x; a2.y += v2.y; a2.z += v2.z; a2.w += v2.w;
        a3.x += v3.x; a3.y += v3.y; a3.z += v3.z; a3.w += v3.w;
    }
    for (; e < end; e++) {
        float4 v = __ldg(base + (size_t)g_csr[e] * 32 + lane);
        a0.x += v.x; a0.y += v.y; a0.z += v.z; a0.w += v.w;
    }
    a0.x += a1.x + a2.x + a3.x + a4.x + a5.x + a6.x + a7.x;
    a0.y += a1.y + a2.y + a3.y + a4.y + a5.y + a6.y + a7.y;
    a0.z += a1.z + a2.z + a3.z + a4.z + a5.z + a6.z + a7.z;
    a0.w += a1.w + a2.w + a3.w + a4.w + a5.w + a6.w + a7.w;
    float inv = 1.0f / (float)((end - beg) > 1 ? (end - beg) : 1);
    a0.x *= inv; a0.y *= inv; a0.z *= inv; a0.w *= inv;
    ((float4*)(out + (size_t)gw * 128))[lane] = a0;
}

// ---- layer-2 fused agg: emb[i] = mean_j p[j] + q[i];  pq rows = [p(64)|q(64)]
__global__ void k_agg_add(const float* __restrict__ pq, float* __restrict__ emb) {
    int gw = (blockIdx.x * blockDim.x + threadIdx.x) >> 5;
    int lane = threadIdx.x & 31;
    if (gw >= NN) return;
    int beg = OFF(gw), end = OFF(gw + 1);
    float2 a0 = make_float2(0.f, 0.f);
    float2 a1 = a0, a2 = a0, a3 = a0, a4 = a0, a5 = a0, a6 = a0, a7 = a0;
    const float2* base = (const float2*)pq;
    int e = beg;
    for (; e + 8 <= end; e += 8) {
        int s0 = g_csr[e],     s1 = g_csr[e + 1], s2 = g_csr[e + 2], s3 = g_csr[e + 3];
        int s4 = g_csr[e + 4], s5 = g_csr[e + 5], s6 = g_csr[e + 6], s7 = g_csr[e + 7];
        float2 v0 = __ldg(base + (size_t)s0 * 64 + lane);
        float2 v1 = __ldg(base + (size_t)s1 * 64 + lane);
        float2 v2 = __ldg(base + (size_t)s2 * 64 + lane);
        float2 v3 = __ldg(base + (size_t)s3 * 64 + lane);
        float2 v4 = __ldg(base + (size_t)s4 * 64 + lane);
        float2 v5 = __ldg(base + (size_t)s5 * 64 + lane);
        float2 v6 = __ldg(base + (size_t)s6 * 64 + lane);
        float2 v7 = __ldg(base + (size_t)s7 * 64 + lane);
        a0.x += v0.x; a0.y += v0.y;  a1.x += v1.x; a1.y += v1.y;
        a2.x += v2.x; a2.y += v2.y;  a3.x += v3.x; a3.y += v3.y;
        a4.x += v4.x; a4.y += v4.y;  a5.x += v5.x; a5.y += v5.y;
        a6.x += v6.x; a6.y += v6.y;  a7.x += v7.x; a7.y += v7.y;
    }
    for (; e + 4 <= end; e += 4) {
        int s0 = g_csr[e], s1 = g_csr[e + 1], s2 = g_csr[e + 2], s3 = g_csr[e + 3];
        float2 v0 = __ldg(base + (size_t)s0 * 64 + lane);
        float2 v1 = __ldg(base + (size_t)s1 * 64 + lane);
        float2 v2 = __ldg(base + (size_t)s2 * 64 + lane);
        float2 v3 = __ldg(base + (size_t)s3 * 64 + lane);
        a0.x += v0.x; a0.y += v0.y;  a1.x += v1.x; a1.y += v1.y;
        a2.x += v2.x; a2.y += v2.y;  a3.x += v3.x; a3.y += v3.y;
    }
    for (; e < end; e++) {
        float2 v = __ldg(base + (size_t)g_csr[e] * 64 + lane);
        a0.x += v.x; a0.y += v.y;
    }
    a0.x += a1.x + a2.x + a3.x + a4.x + a5.x + a6.x + a7.x;
    a0.y += a1.y + a2.y + a3.y + a4.y + a5.y + a6.y + a7.y;
    float inv = 1.0f / (float)((end - beg) > 1 ? (end - beg) : 1);
    float2 q = __ldg(base + (size_t)gw * 64 + 32 + lane);
    *(float2*)(emb + (size_t)gw * 64 + lane * 2) =
        make_float2(a0.x * inv + q.x, a0.y * inv + q.y);
}

// ---------------- tensor-core GEMM: bf16 hi/lo split, fp32 accum ----------
__device__ __forceinline__ void mma_bf16(float4& c, const unsigned* a, const unsigned* b) {
    asm volatile(
        "mma.sync.aligned.m16n8k16.row.col.f32.bf16.bf16.f32 "
        "{%0,%1,%2,%3}, {%4,%5,%6,%7}, {%8,%9}, {%0,%1,%2,%3};"
        : "+f"(c.x), "+f"(c.y), "+f"(c.z), "+f"(c.w)
        : "r"(a[0]), "r"(a[1]), "r"(a[2]), "r"(a[3]), "r"(b[0]), "r"(b[1]));
}

__device__ __forceinline__ void ldsm4(unsigned* r, const bf16* p) {
    unsigned addr = (unsigned)__cvta_generic_to_shared(p);
    asm volatile("ldmatrix.sync.aligned.m8n8.x4.shared.b16 {%0,%1,%2,%3}, [%4];"
                 : "=r"(r[0]), "=r"(r[1]), "=r"(r[2]), "=r"(r[3]) : "r"(addr));
}

// C[M, NC] = act( A1 @ W1^T + A2 @ W2^T + bias + Cin ), W in (hi, lo) bf16.
template <int BN, int NWN>
__global__ __launch_bounds__(NWN * 64) void k_gemm(
    const float* __restrict__ A1, const bf16* __restrict__ W1h,
    const bf16* __restrict__ W1l, int K1,
    const float* __restrict__ A2, const bf16* __restrict__ W2h,
    const bf16* __restrict__ W2l, int K2,
    const float* __restrict__ bias, const float* __restrict__ Cin,
    float* __restrict__ C, int M, int NC, int relu) {
    constexpr int THREADS = NWN * 64;
    constexpr int LDA = 40;
    __shared__ bf16 Ah[128 * LDA], Al[128 * LDA];
    __shared__ bf16 Bh[BN * LDA],  Bl[BN * LDA];

    int tid = threadIdx.x, lane = tid & 31, w = tid >> 5;
    int g = lane >> 2, tg = lane & 3;
    int lr = lane & 15, lc = (lane >> 4) * 8;
    int wm0 = (w / NWN) * 64, wn0 = (w % NWN) * 32;
    int row0 = blockIdx.x * 128, col0 = blockIdx.y * BN;

    float4 acc[4][4];
    #pragma unroll
    for (int i = 0; i < 4; i++)
        #pragma unroll
        for (int j = 0; j < 4; j++) acc[i][j] = make_float4(0.f, 0.f, 0.f, 0.f);

    #pragma unroll 1
    for (int pass = 0; pass < 2; pass++) {
        const float* A = pass ? A2 : A1;
        const bf16* Wh = pass ? W2h : W1h;
        const bf16* Wl_ = pass ? W2l : W1l;
        int K = pass ? K2 : K1;
        if (A == nullptr) break;
        for (int kt = 0; kt < K; kt += 32) {
            #pragma unroll
            for (int v = 0; v < 1024; v += THREADS) {
                int id = v + tid;
                int m = id >> 3, kq = id & 7;
                int r = row0 + m;
                float4 val = make_float4(0.f, 0.f, 0.f, 0.f);
                if (r < M) val = *(const float4*)(A + (size_t)r * K + kt + kq * 4);
                bf16 h0 = __float2bfloat16(val.x), h1 = __float2bfloat16(val.y);
                bf16 h2 = __float2bfloat16(val.z), h3 = __float2bfloat16(val.w);
                *(__nv_bfloat162*)&Ah[m * LDA + kq * 4]     = __halves2bfloat162(h0, h1);
                *(__nv_bfloat162*)&Ah[m * LDA + kq * 4 + 2] = __halves2bfloat162(h2, h3);
                bf16 l0 = __float2bfloat16(val.x - __bfloat162float(h0));
                bf16 l1 = __float2bfloat16(val.y - __bfloat162float(h1));
                bf16 l2 = __float2bfloat16(val.z - __bfloat162float(h2));
                bf16 l3 = __float2bfloat16(val.w - __bfloat162float(h3));
                *(__nv_bfloat162*)&Al[m * LDA + kq * 4]     = __halves2bfloat162(l0, l1);
                *(__nv_bfloat162*)&Al[m * LDA + kq * 4 + 2] = __halves2bfloat162(l2, l3);
            }
            #pragma unroll
            for (int v = 0; v < BN * 4; v += THREADS) {
                int id = v + tid;
                if (id < BN * 4) {
                    int n = id >> 2, kq = id & 3;
                    *(uint4*)&Bh[n * LDA + kq * 8] =
                        *(const uint4*)(Wh + (size_t)(col0 + n) * K + kt + kq * 8);
                    *(uint4*)&Bl[n * LDA + kq * 8] =
                        *(const uint4*)(Wl_ + (size_t)(col0 + n) * K + kt + kq * 8);
                }
            }
            __syncthreads();
            #pragma unroll
            for (int ks = 0; ks < 2; ks++) {
                int k0 = ks * 16;
                unsigned Afh[4][4], Afl[4][4], Bfh[4][2], Bfl[4][2];
                #pragma unroll
                for (int mi = 0; mi < 4; mi++) {
                    int ro = (wm0 + mi * 16 + lr) * LDA + k0 + lc;
                    ldsm4(Afh[mi], &Ah[ro]);
                    ldsm4(Afl[mi], &Al[ro]);
                }
                #pragma unroll
                for (int ni = 0; ni < 4; ni++) {
                    int n = wn0 + ni * 8 + g;
                    Bfh[ni][0] = *(const unsigned*)&Bh[n * LDA + k0 + tg * 2];
                    Bfh[ni][1] = *(const unsigned*)&Bh[n * LDA + k0 + 8 + tg * 2];
                    Bfl[ni][0] = *(const unsigned*)&Bl[n * LDA + k0 + tg * 2];
                    Bfl[ni][1] = *(const unsigned*)&Bl[n * LDA + k0 + 8 + tg * 2];
                }
                #pragma unroll
                for (int mi = 0; mi < 4; mi++)
                    #pragma unroll
                    for (int ni = 0; ni < 4; ni++) {
                        mma_bf16(acc[mi][ni], Afh[mi], Bfh[ni]);
                        mma_bf16(acc[mi][ni], Afh[mi], Bfl[ni]);
                        mma_bf16(acc[mi][ni], Afl[mi], Bfh[ni]);
                    }
            }
            __syncthreads();
        }
    }

    // epilogue
    #pragma unroll
    for (int ni = 0; ni < 4; ni++) {
        int col = col0 + wn0 + ni * 8 + tg * 2;
        float b0 = bias ? bias[col] : 0.f, b1 = bias ? bias[col + 1] : 0.f;
        #pragma unroll
        for (int mi = 0; mi < 4; mi++) {
            int ra = row0 + wm0 + mi * 16 + g;
            float2 v0 = make_float2(acc[mi][ni].x + b0, acc[mi][ni].y + b1);
            float2 v1 = make_float2(acc[mi][ni].z + b0, acc[mi][ni].w + b1);
            if (Cin) {
                if (ra < M) {
                    float2 c0 = *(const float2*)(Cin + (size_t)ra * NC + col);
                    v0.x += c0.x; v0.y += c0.y;
                }
                if (ra + 8 < M) {
                    float2 c1 = *(const float2*)(Cin + (size_t)(ra + 8) * NC + col);
                    v1.x += c1.x; v1.y += c1.y;
                }
            }
            if (relu) {
                v0.x = fmaxf(v0.x, 0.f); v0.y = fmaxf(v0.y, 0.f);
                v1.x = fmaxf(v1.x, 0.f); v1.y = fmaxf(v1.y, 0.f);
            }
            if (ra < M)     *(float2*)(C + (size_t)ra * NC + col) = v0;
            if (ra + 8 < M) *(float2*)(C + (size_t)(ra + 8) * NC + col) = v1;
        }
    }
}

// ---------------- launcher ----------------
extern "C" void kernel_launch(void* const* d_in, const int* in_sizes, int n_in,
                              void* d_out, int out_size) {
    const float* x     = (const float*)d_in[0];
    const void*  ei    = d_in[1];
    const float* W_l1  = (const float*)d_in[2];
    const float* b_l1  = (const float*)d_in[3];
    const float* W_r1  = (const float*)d_in[4];
    const float* W_l2  = (const float*)d_in[5];
    const float* b_l2  = (const float*)d_in[6];
    const float* W_r2  = (const float*)d_in[7];
    const float* fc1_W = (const float*)d_in[8];
    const float* fc1_b = (const float*)d_in[9];
    const float* fc2_W = (const float*)d_in[10];
    const float* fc2_b = (const float*)d_in[11];

    float* emb   = (float*)d_out;                       // [N, 64]
    float* recon = (float*)d_out + (size_t)NN * 64;     // [N, 128]

    float* buf;   cudaGetSymbolAddress((void**)&buf, g_buf);
    float* h;     cudaGetSymbolAddress((void**)&h, g_h);
    float* gr;    cudaGetSymbolAddress((void**)&gr, g_gr);
    float* bias2; cudaGetSymbolAddress((void**)&bias2, g_bias2);
    bf16 *whi, *wlo;
    cudaGetSymbolAddress((void**)&whi, g_whi);
    cudaGetSymbolAddress((void**)&wlo, g_wlo);

    // lazy side stream + fork/join events (created on the uncaptured
    // correctness call; reused identically on every call thereafter)
    static cudaStream_t s_side = nullptr;
    static cudaEvent_t ev_fork = nullptr, ev_join = nullptr;
    if (s_side == nullptr) {
        cudaStreamCreateWithFlags(&s_side, cudaStreamNonBlocking);
        cudaEventCreateWithFlags(&ev_fork, cudaEventDisableTiming);
        cudaEventCreateWithFlags(&ev_join, cudaEventDisableTiming);
    }

    const int aggBlocks = (NN * 32 + 255) / 256;
    const int gmBlocks  = (NN + 127) / 128;
    const int oWl1 = 0, oWr1 = 32768, oW2 = 65536, oF1 = 98304, oF2 = 114688;

    // prep (weights + zero + dtype)
    k_prep<<<(WTOT + 255) / 256, 256>>>((const unsigned*)ei, W_l1, W_r1, W_l2, W_r2,
                                        fc1_W, fc2_W, b_l2);

    // fork: side stream computes Gr = x @ W_r1^T + b_l1 (independent of CSR)
    cudaEventRecord(ev_fork, 0);
    cudaStreamWaitEvent(s_side, ev_fork, 0);
    k_gemm<128, 4><<<dim3(gmBlocks, 2), 256, 0, s_side>>>(
        x, whi + oWr1, wlo + oWr1, 128,
        nullptr, nullptr, nullptr, 0, b_l1, nullptr, gr, NN, 256, 0);
    cudaEventRecord(ev_join, s_side);

    // main: CSR build + agg1 (overlaps with Gr)
    k_hist<<<(EE / 2 + 255) / 256, 256>>>(ei);
    k_scan<<<NBLK, 1024>>>();
    k_scatter<<<(EE / 2 + 255) / 256, 256>>>(ei);
    k_agg128<<<aggBlocks, 256>>>(x, buf);

    // join, then h = relu(mean1 @ W_l1^T + Gr)
    cudaStreamWaitEvent(0, ev_join, 0);
    k_gemm<128, 4><<<dim3(gmBlocks, 2), 256>>>(
        buf, whi + oWl1, wlo + oWl1, 128,
        nullptr, nullptr, nullptr, 0, nullptr, gr, h, NN, 256, 1);

    // Layer 2 (linearity): pq = h @ [W_l2;W_r2]^T + [0|b_l2]; emb = mean(p)+q
    k_gemm<128, 4><<<dim3(gmBlocks, 1), 256>>>(
        h, whi + oW2, wlo + oW2, 256,
        nullptr, nullptr, nullptr, 0, bias2, nullptr, buf, NN, 128, 0);
    k_agg_add<<<aggBlocks, 256>>>(buf, emb);

    // Decoder: hid = relu(emb @ fc1_W^T + fc1_b); recon = hid @ fc2_W^T + fc2_b
    k_gemm<128, 4><<<dim3(gmBlocks, 2), 256>>>(
        emb, whi + oF1, wlo + oF1, 64,
        nullptr, nullptr, nullptr, 0, fc1_b, nullptr, buf, NN, 256, 1);
    k_gemm<128, 4><<<dim3(gmBlocks, 1), 256>>>(
        buf, whi + oF2, wlo + oF2, 256,
        nullptr, nullptr, nullptr, 0, fc2_b, nullptr, recon, NN, 128, 0);
}

// round 13
// speedup vs baseline: 1.0294x; 1.0294x over previous
#include <cuda_runtime.h>
#include <cuda_bf16.h>
#include <cstdint>

#define NN 100000
#define EE 1600000
#define NBLK ((NN + 1023) / 1024)   // 98
#define WTOT 147456                  // total weight elements across 6 matrices

typedef __nv_bfloat16 bf16;

// ---------------- scratch (device globals; no allocation) ----------------
__device__ int      g_is64;
__device__ int      g_deg[NN];
__device__ int      g_off[NN + 1];
__device__ int      g_cursor[NN];
__device__ int      g_bsum[128];
__device__ unsigned g_tick;
__device__ int      g_csr[EE];
__device__ float    g_buf[(size_t)NN * 256];  // mean1 -> pq (reused)
__device__ float    g_h[(size_t)NN * 256];    // hidden after layer 1
__device__ float    g_bias2[128];             // [0(64) | b_l2(64)]
__device__ bf16     g_whi[WTOT], g_wlo[WTOT];

__device__ __forceinline__ int OFF(int i) { return g_off[i] + g_bsum[i >> 10]; }

// ---------------- prep: split weights + zero + dtype detect ----------------
__global__ void k_prep(const unsigned* ei,
                       const float* Wl1, const float* Wr1,
                       const float* Wl2, const float* Wr2,
                       const float* fc1, const float* fc2,
                       const float* bl2) {
    int i = blockIdx.x * blockDim.x + threadIdx.x;
    if (i == 0) {
        int is64 = 1;
        for (int t = 0; t < 1024; t++)
            if (ei[2 * t + 1] != 0u) { is64 = 0; break; }
        g_is64 = is64;
        g_tick = 0u;
    }
    if (i < NN) { g_deg[i] = 0; g_cursor[i] = 0; }
    if (i < 128) g_bias2[i] = (i < 64) ? 0.f : bl2[i - 64];
    if (i < WTOT) {
        const float* src; int off;
        if      (i < 32768)  { src = Wl1; off = 0; }
        else if (i < 65536)  { src = Wr1; off = 32768; }
        else if (i < 81920)  { src = Wl2; off = 65536; }
        else if (i < 98304)  { src = Wr2; off = 81920; }
        else if (i < 114688) { src = fc1; off = 98304; }
        else                 { src = fc2; off = 114688; }
        float a = src[i - off];
        bf16 h = __float2bfloat16(a);
        g_whi[i] = h;
        g_wlo[i] = __float2bfloat16(a - __bfloat162float(h));
    }
}

__device__ __forceinline__ int eidx(const void* ei, int is64, int idx) {
    if (is64) return (int)((const long long*)ei)[idx];
    return ((const int*)ei)[idx];
}

// 2 edges per thread, vector loads of the dst halves
__global__ void k_hist(const void* ei) {
    int t = blockIdx.x * blockDim.x + threadIdx.x;
    int e = t * 2;
    if (e >= EE) return;
    if (g_is64) {
        longlong2 d = __ldg((const longlong2*)((const long long*)ei + EE) + t);
        atomicAdd(&g_deg[(int)d.x], 1);
        atomicAdd(&g_deg[(int)d.y], 1);
    } else {
        int2 d = __ldg((const int2*)((const int*)ei + EE) + t);
        atomicAdd(&g_deg[d.x], 1);
        atomicAdd(&g_deg[d.y], 1);
    }
}

// ---- fused scan: per-block local scan + decoupled last-block base scan ----
__global__ void k_scan() {
    __shared__ int ws[32];
    __shared__ unsigned last;
    int tid = threadIdx.x, lane = tid & 31, warp = tid >> 5;
    int i = blockIdx.x * 1024 + tid;
    int v = (i < NN) ? g_deg[i] : 0;
    int x = v;
    #pragma unroll
    for (int o = 1; o < 32; o <<= 1) {
        int y = __shfl_up_sync(0xFFFFFFFFu, x, o);
        if (lane >= o) x += y;
    }
    if (lane == 31) ws[warp] = x;
    __syncthreads();
    if (tid < 32) {
        int s = ws[tid];
        #pragma unroll
        for (int o = 1; o < 32; o <<= 1) {
            int y = __shfl_up_sync(0xFFFFFFFFu, s, o);
            if (tid >= o) s += y;
        }
        ws[tid] = s;
    }
    __syncthreads();
    int excl = (warp ? ws[warp - 1] : 0) + (x - v);
    if (i <= NN) g_off[i] = excl;
    if (tid == 0) g_bsum[blockIdx.x] = ws[31];
    __threadfence();
    __syncthreads();
    if (tid == 0) last = (atomicAdd(&g_tick, 1u) == (unsigned)(NBLK - 1)) ? 1u : 0u;
    __syncthreads();
    if (last && tid < 128) {
        int t = tid, ln = t & 31, wp = t >> 5;
        int bv = (t < NBLK) ? *(volatile int*)&g_bsum[t] : 0;
        int bx = bv;
        #pragma unroll
        for (int o = 1; o < 32; o <<= 1) {
            int y = __shfl_up_sync(0xFFFFFFFFu, bx, o);
            if (ln >= o) bx += y;
        }
        if (ln == 31) ws[wp] = bx;
        __syncwarp();
        if (t == 0) { int a = ws[0]; ws[4] = 0; ws[5] = a; ws[6] = a + ws[1]; ws[7] = a + ws[1] + ws[2]; }
        __syncthreads();
        if (t < NBLK) g_bsum[t] = ws[4 + wp] + bx - bv;
    }
}

// 2 edges per thread, vectorized
__global__ void k_scatter(const void* ei) {
    int t = blockIdx.x * blockDim.x + threadIdx.x;
    int e = t * 2;
    if (e >= EE) return;
    if (g_is64) {
        longlong2 s = __ldg((const longlong2*)((const long long*)ei) + t);
        longlong2 d = __ldg((const longlong2*)((const long long*)ei + EE) + t);
        int p0 = atomicAdd(&g_cursor[(int)d.x], 1);
        g_csr[OFF((int)d.x) + p0] = (int)s.x;
        int p1 = atomicAdd(&g_cursor[(int)d.y], 1);
        g_csr[OFF((int)d.y) + p1] = (int)s.y;
    } else {
        int2 s = __ldg((const int2*)((const int*)ei) + t);
        int2 d = __ldg((const int2*)((const int*)ei + EE) + t);
        int p0 = atomicAdd(&g_cursor[d.x], 1);
        g_csr[OFF(d.x) + p0] = s.x;
        int p1 = atomicAdd(&g_cursor[d.y], 1);
        g_csr[OFF(d.y) + p1] = s.y;
    }
}

// ---------------- mean aggregation (F=128): warp/node, 8-way MLP ----------
__global__ void k_agg128(const float* __restrict__ X, float* __restrict__ out) {
    int gw = (blockIdx.x * blockDim.x + threadIdx.x) >> 5;
    int lane = threadIdx.x & 31;
    if (gw >= NN) return;
    int beg = OFF(gw), end = OFF(gw + 1);
    float4 a0 = make_float4(0.f, 0.f, 0.f, 0.f);
    float4 a1 = a0, a2 = a0, a3 = a0, a4 = a0, a5 = a0, a6 = a0, a7 = a0;
    const float4* base = (const float4*)X;
    int e = beg;
    for (; e + 8 <= end; e += 8) {
        int s0 = g_csr[e],     s1 = g_csr[e + 1], s2 = g_csr[e + 2], s3 = g_csr[e + 3];
        int s4 = g_csr[e + 4], s5 = g_csr[e + 5], s6 = g_csr[e + 6], s7 = g_csr[e + 7];
        float4 v0 = __ldg(base + (size_t)s0 * 32 + lane);
        float4 v1 = __ldg(base + (size_t)s1 * 32 + lane);
        float4 v2 = __ldg(base + (size_t)s2 * 32 + lane);
        float4 v3 = __ldg(base + (size_t)s3 * 32 + lane);
        float4 v4 = __ldg(base + (size_t)s4 * 32 + lane);
        float4 v5 = __ldg(base + (size_t)s5 * 32 + lane);
        float4 v6 = __ldg(base + (size_t)s6 * 32 + lane);
        float4 v7 = __ldg(base + (size_t)s7 * 32 + lane);
        a0.x += v0.x; a0.y += v0.y; a0.z += v0.z; a0.w += v0.w;
        a1.x += v1.x; a1.y += v1.y; a1.z += v1.z; a1.w += v1.w;
        a2.x += v2.x; a2.y += v2.y; a2.z += v2.z; a2.w += v2.w;
        a3.x += v3.x; a3.y += v3.y; a3.z += v3.z; a3.w += v3.w;
        a4.x += v4.x; a4.y += v4.y; a4.z += v4.z; a4.w += v4.w;
        a5.x += v5.x; a5.y += v5.y; a5.z += v5.z; a5.w += v5.w;
        a6.x += v6.x; a6.y += v6.y; a6.z += v6.z; a6.w += v6.w;
        a7.x += v7.x; a7.y += v7.y; a7.z += v7.z; a7.w += v7.w;
    }
    for (; e + 4 <= end; e += 4) {
        int s0 = g_csr[e], s1 = g_csr[e + 1], s2 = g_csr[e + 2], s3 = g_csr[e + 3];
        float4 v0 = __ldg(base + (size_t)s0 * 32 + lane);
        float4 v1 = __ldg(base + (size_t)s1 * 32 + lane);
        float4 v2 = __ldg(base + (size_t)s2 * 32 + lane);
        float4 v3 = __ldg(base + (size_t)s3 * 32 + lane);
        a0.x += v0.x; a0.y += v0.y; a0.z += v0.z; a0.w += v0.w;
        a1.x += v1.x; a1.y += v1.y; a1.z += v1.z; a1.w += v1.w;
        a2.x += v2.x; a2.y += v2.y; a2.z += v2.z; a2.w += v2.w;
        a3.x += v3.x; a3.y += v3.y; a3.z += v3.z; a3.w += v3.w;
    }
    for (; e < end; e++) {
        float4 v = __ldg(base + (size_t)g_csr[e] * 32 + lane);
        a0.x += v.x; a0.y += v.y; a0.z += v.z; a0.w += v.w;
    }
    a0.x += a1.x + a2.x + a3.x + a4.x + a5.x + a6.x + a7.x;
    a0.y += a1.y + a2.y + a3.y + a4.y + a5.y + a6.y + a7.y;
    a0.z += a1.z + a2.z + a3.z + a4.z + a5.z + a6.z + a7.z;
    a0.w += a1.w + a2.w + a3.w + a4.w + a5.w + a6.w + a7.w;
    float inv = 1.0f / (float)((end - beg) > 1 ? (end - beg) : 1);
    a0.x *= inv; a0.y *= inv; a0.z *= inv; a0.w *= inv;
    ((float4*)(out + (size_t)gw * 128))[lane] = a0;
}

// ---- layer-2 fused agg: emb[i] = mean_j p[j] + q[i];  pq rows = [p(64)|q(64)]
__global__ void k_agg_add(const float* __restrict__ pq, float* __restrict__ emb) {
    int gw = (blockIdx.x * blockDim.x + threadIdx.x) >> 5;
    int lane = threadIdx.x & 31;
    if (gw >= NN) return;
    int beg = OFF(gw), end = OFF(gw + 1);
    float2 a0 = make_float2(0.f, 0.f);
    float2 a1 = a0, a2 = a0, a3 = a0, a4 = a0, a5 = a0, a6 = a0, a7 = a0;
    const float2* base = (const float2*)pq;
    int e = beg;
    for (; e + 8 <= end; e += 8) {
        int s0 = g_csr[e],     s1 = g_csr[e + 1], s2 = g_csr[e + 2], s3 = g_csr[e + 3];
        int s4 = g_csr[e + 4], s5 = g_csr[e + 5], s6 = g_csr[e + 6], s7 = g_csr[e + 7];
        float2 v0 = __ldg(base + (size_t)s0 * 64 + lane);
        float2 v1 = __ldg(base + (size_t)s1 * 64 + lane);
        float2 v2 = __ldg(base + (size_t)s2 * 64 + lane);
        float2 v3 = __ldg(base + (size_t)s3 * 64 + lane);
        float2 v4 = __ldg(base + (size_t)s4 * 64 + lane);
        float2 v5 = __ldg(base + (size_t)s5 * 64 + lane);
        float2 v6 = __ldg(base + (size_t)s6 * 64 + lane);
        float2 v7 = __ldg(base + (size_t)s7 * 64 + lane);
        a0.x += v0.x; a0.y += v0.y;  a1.x += v1.x; a1.y += v1.y;
        a2.x += v2.x; a2.y += v2.y;  a3.x += v3.x; a3.y += v3.y;
        a4.x += v4.x; a4.y += v4.y;  a5.x += v5.x; a5.y += v5.y;
        a6.x += v6.x; a6.y += v6.y;  a7.x += v7.x; a7.y += v7.y;
    }
    for (; e + 4 <= end; e += 4) {
        int s0 = g_csr[e], s1 = g_csr[e + 1], s2 = g_csr[e + 2], s3 = g_csr[e + 3];
        float2 v0 = __ldg(base + (size_t)s0 * 64 + lane);
        float2 v1 = __ldg(base + (size_t)s1 * 64 + lane);
        float2 v2 = __ldg(base + (size_t)s2 * 64 + lane);
        float2 v3 = __ldg(base + (size_t)s3 * 64 + lane);
        a0.x += v0.x; a0.y += v0.y;  a1.x += v1.x; a1.y += v1.y;
        a2.x += v2.x; a2.y += v2.y;  a3.x += v3.x; a3.y += v3.y;
    }
    for (; e < end; e++) {
        float2 v = __ldg(base + (size_t)g_csr[e] * 64 + lane);
        a0.x += v.x; a0.y += v.y;
    }
    a0.x += a1.x + a2.x + a3.x + a4.x + a5.x + a6.x + a7.x;
    a0.y += a1.y + a2.y + a3.y + a4.y + a5.y + a6.y + a7.y;
    float inv = 1.0f / (float)((end - beg) > 1 ? (end - beg) : 1);
    float2 q = __ldg(base + (size_t)gw * 64 + 32 + lane);
    *(float2*)(emb + (size_t)gw * 64 + lane * 2) =
        make_float2(a0.x * inv + q.x, a0.y * inv + q.y);
}

// ---------------- tensor-core GEMM: bf16 hi/lo split, fp32 accum ----------
__device__ __forceinline__ void mma_bf16(float4& c, const unsigned* a, const unsigned* b) {
    asm volatile(
        "mma.sync.aligned.m16n8k16.row.col.f32.bf16.bf16.f32 "
        "{%0,%1,%2,%3}, {%4,%5,%6,%7}, {%8,%9}, {%0,%1,%2,%3};"
        : "+f"(c.x), "+f"(c.y), "+f"(c.z), "+f"(c.w)
        : "r"(a[0]), "r"(a[1]), "r"(a[2]), "r"(a[3]), "r"(b[0]), "r"(b[1]));
}

__device__ __forceinline__ void ldsm4(unsigned* r, const bf16* p) {
    unsigned addr = (unsigned)__cvta_generic_to_shared(p);
    asm volatile("ldmatrix.sync.aligned.m8n8.x4.shared.b16 {%0,%1,%2,%3}, [%4];"
                 : "=r"(r[0]), "=r"(r[1]), "=r"(r[2]), "=r"(r[3]) : "r"(addr));
}

// C[M, NC] = act( A1 @ W1^T + A2 @ W2^T + bias ), W in (hi, lo) bf16.
template <int BN, int NWN>
__global__ __launch_bounds__(NWN * 64) void k_gemm(
    const float* __restrict__ A1, const bf16* __restrict__ W1h,
    const bf16* __restrict__ W1l, int K1,
    const float* __restrict__ A2, const bf16* __restrict__ W2h,
    const bf16* __restrict__ W2l, int K2,
    const float* __restrict__ bias, float* __restrict__ C,
    int M, int NC, int relu) {
    constexpr int THREADS = NWN * 64;
    constexpr int LDA = 40;
    __shared__ bf16 Ah[128 * LDA], Al[128 * LDA];
    __shared__ bf16 Bh[BN * LDA],  Bl[BN * LDA];

    int tid = threadIdx.x, lane = tid & 31, w = tid >> 5;
    int g = lane >> 2, tg = lane & 3;
    int lr = lane & 15, lc = (lane >> 4) * 8;
    int wm0 = (w / NWN) * 64, wn0 = (w % NWN) * 32;
    int row0 = blockIdx.x * 128, col0 = blockIdx.y * BN;

    float4 acc[4][4];
    #pragma unroll
    for (int i = 0; i < 4; i++)
        #pragma unroll
        for (int j = 0; j < 4; j++) acc[i][j] = make_float4(0.f, 0.f, 0.f, 0.f);

    #pragma unroll 1
    for (int pass = 0; pass < 2; pass++) {
        const float* A = pass ? A2 : A1;
        const bf16* Wh = pass ? W2h : W1h;
        const bf16* Wl_ = pass ? W2l : W1l;
        int K = pass ? K2 : K1;
        if (A == nullptr) break;
        for (int kt = 0; kt < K; kt += 32) {
            #pragma unroll
            for (int v = 0; v < 1024; v += THREADS) {
                int id = v + tid;
                int m = id >> 3, kq = id & 7;
                int r = row0 + m;
                float4 val = make_float4(0.f, 0.f, 0.f, 0.f);
                if (r < M) val = *(const float4*)(A + (size_t)r * K + kt + kq * 4);
                bf16 h0 = __float2bfloat16(val.x), h1 = __float2bfloat16(val.y);
                bf16 h2 = __float2bfloat16(val.z), h3 = __float2bfloat16(val.w);
                *(__nv_bfloat162*)&Ah[m * LDA + kq * 4]     = __halves2bfloat162(h0, h1);
                *(__nv_bfloat162*)&Ah[m * LDA + kq * 4 + 2] = __halves2bfloat162(h2, h3);
                bf16 l0 = __float2bfloat16(val.x - __bfloat162float(h0));
                bf16 l1 = __float2bfloat16(val.y - __bfloat162float(h1));
                bf16 l2 = __float2bfloat16(val.z - __bfloat162float(h2));
                bf16 l3 = __float2bfloat16(val.w - __bfloat162float(h3));
                *(__nv_bfloat162*)&Al[m * LDA + kq * 4]     = __halves2bfloat162(l0, l1);
                *(__nv_bfloat162*)&Al[m * LDA + kq * 4 + 2] = __halves2bfloat162(l2, l3);
            }
            #pragma unroll
            for (int v = 0; v < BN * 4; v += THREADS) {
                int id = v + tid;
                if (id < BN * 4) {
                    int n = id >> 2, kq = id & 3;
                    *(uint4*)&Bh[n * LDA + kq * 8] =
                        *(const uint4*)(Wh + (size_t)(col0 + n) * K + kt + kq * 8);
                    *(uint4*)&Bl[n * LDA + kq * 8] =
                        *(const uint4*)(Wl_ + (size_t)(col0 + n) * K + kt + kq * 8);
                }
            }
            __syncthreads();
            #pragma unroll
            for (int ks = 0; ks < 2; ks++) {
                int k0 = ks * 16;
                unsigned Afh[4][4], Afl[4][4], Bfh[4][2], Bfl[4][2];
                #pragma unroll
                for (int mi = 0; mi < 4; mi++) {
                    int ro = (wm0 + mi * 16 + lr) * LDA + k0 + lc;
                    ldsm4(Afh[mi], &Ah[ro]);
                    ldsm4(Afl[mi], &Al[ro]);
                }
                #pragma unroll
                for (int ni = 0; ni < 4; ni++) {
                    int n = wn0 + ni * 8 + g;
                    Bfh[ni][0] = *(const unsigned*)&Bh[n * LDA + k0 + tg * 2];
                    Bfh[ni][1] = *(const unsigned*)&Bh[n * LDA + k0 + 8 + tg * 2];
                    Bfl[ni][0] = *(const unsigned*)&Bl[n * LDA + k0 + tg * 2];
                    Bfl[ni][1] = *(const unsigned*)&Bl[n * LDA + k0 + 8 + tg * 2];
                }
                #pragma unroll
                for (int mi = 0; mi < 4; mi++)
                    #pragma unroll
                    for (int ni = 0; ni < 4; ni++) {
                        mma_bf16(acc[mi][ni], Afh[mi], Bfh[ni]);
                        mma_bf16(acc[mi][ni], Afh[mi], Bfl[ni]);
                        mma_bf16(acc[mi][ni], Afl[mi], Bfh[ni]);
                    }
            }
            __syncthreads();
        }
    }

    #pragma unroll
    for (int ni = 0; ni < 4; ni++) {
        int col = col0 + wn0 + ni * 8 + tg * 2;
        float b0 = bias[col], b1 = bias[col + 1];
        #pragma unroll
        for (int mi = 0; mi < 4; mi++) {
            int ra = row0 + wm0 + mi * 16 + g;
            float2 v0 = make_float2(acc[mi][ni].x + b0, acc[mi][ni].y + b1);
            float2 v1 = make_float2(acc[mi][ni].z + b0, acc[mi][ni].w + b1);
            if (relu) {
                v0.x = fmaxf(v0.x, 0.f); v0.y = fmaxf(v0.y, 0.f);
                v1.x = fmaxf(v1.x, 0.f); v1.y = fmaxf(v1.y, 0.f);
            }
            if (ra < M)     *(float2*)(C + (size_t)ra * NC + col) = v0;
            if (ra + 8 < M) *(float2*)(C + (size_t)(ra + 8) * NC + col) = v1;
        }
    }
}

// ============ fused decoder: recon = relu(emb@fc1^T + b1)@fc2^T + b2 =======
// Phase 1: hid(128x256) into smem bf16 hi/lo planes. Phase 2: K=256 GEMM.
#define LDA2 264   // halves; 528B row stride, conflict-free ldmatrix
__global__ __launch_bounds__(256) void k_dec(
    const float* __restrict__ emb,
    const bf16* __restrict__ F1h, const bf16* __restrict__ F1l,
    const float* __restrict__ f1b,
    const bf16* __restrict__ F2h, const bf16* __restrict__ F2l,
    const float* __restrict__ f2b,
    float* __restrict__ recon, int M) {
    extern __shared__ __align__(16) bf16 dsm[];
    bf16* hidH = dsm;                   // 128*264
    bf16* hidL = dsm + 128 * LDA2;
    bf16* sAh  = dsm + 2 * 128 * LDA2;  // 128*40
    bf16* sAl  = sAh + 128 * 40;
    bf16* sBh  = sAl + 128 * 40;        // 128*40
    bf16* sBl  = sBh + 128 * 40;

    int tid = threadIdx.x, lane = tid & 31, w = tid >> 5;
    int g = lane >> 2, tg = lane & 3;
    int lr = lane & 15, lc = (lane >> 4) * 8;
    int wm0 = (w >> 2) * 64, wn0 = (w & 3) * 32;
    int row0 = blockIdx.x * 128;

    float4 acc[4][4];

    // ---------------- phase 1: two column halves of hid ----------------
    #pragma unroll 1
    for (int cb = 0; cb < 2; cb++) {
        #pragma unroll
        for (int i = 0; i < 4; i++)
            #pragma unroll
            for (int j = 0; j < 4; j++) acc[i][j] = make_float4(0.f, 0.f, 0.f, 0.f);
        #pragma unroll 1
        for (int kt = 0; kt < 64; kt += 32) {
            #pragma unroll
            for (int v = 0; v < 1024; v += 256) {
                int id = v + tid;
                int m = id >> 3, kq = id & 7;
                int r = row0 + m;
                float4 val = make_float4(0.f, 0.f, 0.f, 0.f);
                if (r < M) val = *(const float4*)(emb + (size_t)r * 64 + kt + kq * 4);
                bf16 h0 = __float2bfloat16(val.x), h1 = __float2bfloat16(val.y);
                bf16 h2 = __float2bfloat16(val.z), h3 = __float2bfloat16(val.w);
                *(__nv_bfloat162*)&sAh[m * 40 + kq * 4]     = __halves2bfloat162(h0, h1);
                *(__nv_bfloat162*)&sAh[m * 40 + kq * 4 + 2] = __halves2bfloat162(h2, h3);
                bf16 l0 = __float2bfloat16(val.x - __bfloat162float(h0));
                bf16 l1 = __float2bfloat16(val.y - __bfloat162float(h1));
                bf16 l2 = __float2bfloat16(val.z - __bfloat162float(h2));
                bf16 l3 = __float2bfloat16(val.w - __bfloat162float(h3));
                *(__nv_bfloat162*)&sAl[m * 40 + kq * 4]     = __halves2bfloat162(l0, l1);
                *(__nv_bfloat162*)&sAl[m * 40 + kq * 4 + 2] = __halves2bfloat162(l2, l3);
            }
            #pragma unroll
            for (int v = 0; v < 512; v += 256) {
                int id = v + tid;
                int n = id >> 2, kq = id & 3;
                *(uint4*)&sBh[n * 40 + kq * 8] =
                    *(const uint4*)(F1h + (size_t)(cb * 128 + n) * 64 + kt + kq * 8);
                *(uint4*)&sBl[n * 40 + kq * 8] =
                    *(const uint4*)(F1l + (size_t)(cb * 128 + n) * 64 + kt + kq * 8);
            }
            __syncthreads();
            #pragma unroll
            for (int ks = 0; ks < 2; ks++) {
                int k0 = ks * 16;
                unsigned Afh[4][4], Afl[4][4], Bfh[4][2], Bfl[4][2];
                #pragma unroll
                for (int mi = 0; mi < 4; mi++) {
                    int ro = (wm0 + mi * 16 + lr) * 40 + k0 + lc;
                    ldsm4(Afh[mi], &sAh[ro]);
                    ldsm4(Afl[mi], &sAl[ro]);
                }
                #pragma unroll
                for (int ni = 0; ni < 4; ni++) {
                    int n = wn0 + ni * 8 + g;
                    Bfh[ni][0] = *(const unsigned*)&sBh[n * 40 + k0 + tg * 2];
                    Bfh[ni][1] = *(const unsigned*)&sBh[n * 40 + k0 + 8 + tg * 2];
                    Bfl[ni][0] = *(const unsigned*)&sBl[n * 40 + k0 + tg * 2];
                    Bfl[ni][1] = *(const unsigned*)&sBl[n * 40 + k0 + 8 + tg * 2];
                }
                #pragma unroll
                for (int mi = 0; mi < 4; mi++)
                    #pragma unroll
                    for (int ni = 0; ni < 4; ni++) {
                        mma_bf16(acc[mi][ni], Afh[mi], Bfh[ni]);
                        mma_bf16(acc[mi][ni], Afh[mi], Bfl[ni]);
                        mma_bf16(acc[mi][ni], Afl[mi], Bfh[ni]);
                    }
            }
            __syncthreads();
        }
        // epilogue: relu + split into hid planes (smem)
        #pragma unroll
        for (int ni = 0; ni < 4; ni++) {
            int col = cb * 128 + wn0 + ni * 8 + tg * 2;
            float b0 = f1b[col], b1 = f1b[col + 1];
            #pragma unroll
            for (int mi = 0; mi < 4; mi++) {
                int rl0 = wm0 + mi * 16 + g;
                float p0 = fmaxf(acc[mi][ni].x + b0, 0.f);
                float p1 = fmaxf(acc[mi][ni].y + b1, 0.f);
                float p2 = fmaxf(acc[mi][ni].z + b0, 0.f);
                float p3 = fmaxf(acc[mi][ni].w + b1, 0.f);
                bf16 h0 = __float2bfloat16(p0), h1 = __float2bfloat16(p1);
                bf16 h2 = __float2bfloat16(p2), h3 = __float2bfloat16(p3);
                *(__nv_bfloat162*)&hidH[rl0 * LDA2 + col]       = __halves2bfloat162(h0, h1);
                *(__nv_bfloat162*)&hidH[(rl0 + 8) * LDA2 + col] = __halves2bfloat162(h2, h3);
                bf16 l0 = __float2bfloat16(p0 - __bfloat162float(h0));
                bf16 l1 = __float2bfloat16(p1 - __bfloat162float(h1));
                bf16 l2 = __float2bfloat16(p2 - __bfloat162float(h2));
                bf16 l3 = __float2bfloat16(p3 - __bfloat162float(h3));
                *(__nv_bfloat162*)&hidL[rl0 * LDA2 + col]       = __halves2bfloat162(l0, l1);
                *(__nv_bfloat162*)&hidL[(rl0 + 8) * LDA2 + col] = __halves2bfloat162(l2, l3);
            }
        }
        __syncthreads();
    }

    // ---------------- phase 2: recon = hid @ fc2^T + f2b ----------------
    #pragma unroll
    for (int i = 0; i < 4; i++)
        #pragma unroll
        for (int j = 0; j < 4; j++) acc[i][j] = make_float4(0.f, 0.f, 0.f, 0.f);
    #pragma unroll 1
    for (int kt = 0; kt < 256; kt += 32) {
        #pragma unroll
        for (int v = 0; v < 512; v += 256) {
            int id = v + tid;
            int n = id >> 2, kq = id & 3;
            *(uint4*)&sBh[n * 40 + kq * 8] =
                *(const uint4*)(F2h + (size_t)n * 256 + kt + kq * 8);
            *(uint4*)&sBl[n * 40 + kq * 8] =
                *(const uint4*)(F2l + (size_t)n * 256 + kt + kq * 8);
        }
        __syncthreads();
        #pragma unroll
        for (int ks = 0; ks < 2; ks++) {
            int k0 = ks * 16;
            unsigned Afh[4][4], Afl[4][4], Bfh[4][2], Bfl[4][2];
            #pragma unroll
            for (int mi = 0; mi < 4; mi++) {
                int ro = (wm0 + mi * 16 + lr) * LDA2 + kt + k0 + lc;
                ldsm4(Afh[mi], &hidH[ro]);
                ldsm4(Afl[mi], &hidL[ro]);
            }
            #pragma unroll
            for (int ni = 0; ni < 4; ni++) {
                int n = wn0 + ni * 8 + g;
                Bfh[ni][0] = *(const unsigned*)&sBh[n * 40 + k0 + tg * 2];
                Bfh[ni][1] = *(const unsigned*)&sBh[n * 40 + k0 + 8 + tg * 2];
                Bfl[ni][0] = *(const unsigned*)&sBl[n * 40 + k0 + tg * 2];
                Bfl[ni][1] = *(const unsigned*)&sBl[n * 40 + k0 + 8 + tg * 2];
            }
            #pragma unroll
            for (int mi = 0; mi < 4; mi++)
                #pragma unroll
                for (int ni = 0; ni < 4; ni++) {
                    mma_bf16(acc[mi][ni], Afh[mi], Bfh[ni]);
                    mma_bf16(acc[mi][ni], Afh[mi], Bfl[ni]);
                    mma_bf16(acc[mi][ni], Afl[mi], Bfh[ni]);
                }
        }
        __syncthreads();
    }
    #pragma unroll
    for (int ni = 0; ni < 4; ni++) {
        int col = wn0 + ni * 8 + tg * 2;
        float b0 = f2b[col], b1 = f2b[col + 1];
        #pragma unroll
        for (int mi = 0; mi < 4; mi++) {
            int ra = row0 + wm0 + mi * 16 + g;
            if (ra < M)
                *(float2*)(recon + (size_t)ra * 128 + col) =
                    make_float2(acc[mi][ni].x + b0, acc[mi][ni].y + b1);
            if (ra + 8 < M)
                *(float2*)(recon + (size_t)(ra + 8) * 128 + col) =
                    make_float2(acc[mi][ni].z + b0, acc[mi][ni].w + b1);
        }
    }
}

// ---------------- launcher ----------------
extern "C" void kernel_launch(void* const* d_in, const int* in_sizes, int n_in,
                              void* d_out, int out_size) {
    const float* x     = (const float*)d_in[0];
    const void*  ei    = d_in[1];
    const float* W_l1  = (const float*)d_in[2];
    const float* b_l1  = (const float*)d_in[3];
    const float* W_r1  = (const float*)d_in[4];
    const float* W_l2  = (const float*)d_in[5];
    const float* b_l2  = (const float*)d_in[6];
    const float* W_r2  = (const float*)d_in[7];
    const float* fc1_W = (const float*)d_in[8];
    const float* fc1_b = (const float*)d_in[9];
    const float* fc2_W = (const float*)d_in[10];
    const float* fc2_b = (const float*)d_in[11];

    float* emb   = (float*)d_out;                       // [N, 64]
    float* recon = (float*)d_out + (size_t)NN * 64;     // [N, 128]

    float* buf;   cudaGetSymbolAddress((void**)&buf, g_buf);
    float* h;     cudaGetSymbolAddress((void**)&h, g_h);
    float* bias2; cudaGetSymbolAddress((void**)&bias2, g_bias2);
    bf16 *whi, *wlo;
    cudaGetSymbolAddress((void**)&whi, g_whi);
    cudaGetSymbolAddress((void**)&wlo, g_wlo);

    const int DSM = (2 * 128 * LDA2 + 4 * 128 * 40) * (int)sizeof(bf16);  // 176128
    static int attr_set = 0;
    if (!attr_set) {
        cudaFuncSetAttribute(k_dec, cudaFuncAttributeMaxDynamicSharedMemorySize, DSM);
        attr_set = 1;
    }

    // CSR build + weight split
    k_prep<<<(WTOT + 255) / 256, 256>>>((const unsigned*)ei, W_l1, W_r1, W_l2, W_r2,
                                        fc1_W, fc2_W, b_l2);
    k_hist<<<(EE / 2 + 255) / 256, 256>>>(ei);
    k_scan<<<NBLK, 1024>>>();
    k_scatter<<<(EE / 2 + 255) / 256, 256>>>(ei);

    const int aggBlocks = (NN * 32 + 255) / 256;
    const int gmBlocks  = (NN + 127) / 128;
    const int oWl1 = 0, oWr1 = 32768, oW2 = 65536, oF1 = 98304, oF2 = 114688;

    // Layer 1: h = relu(mean1 @ W_l1^T + x @ W_r1^T + b_l1)
    k_agg128<<<aggBlocks, 256>>>(x, buf);
    k_gemm<128, 4><<<dim3(gmBlocks, 2), 256>>>(
        buf, whi + oWl1, wlo + oWl1, 128,
        x,   whi + oWr1, wlo + oWr1, 128, b_l1, h, NN, 256, 1);

    // Layer 2 (linearity): pq = h @ [W_l2;W_r2]^T + [0|b_l2]; emb = mean(p)+q
    k_gemm<128, 4><<<dim3(gmBlocks, 1), 256>>>(
        h, whi + oW2, wlo + oW2, 256,
        nullptr, nullptr, nullptr, 0, bias2, buf, NN, 128, 0);
    k_agg_add<<<aggBlocks, 256>>>(buf, emb);

    // Fused decoder: recon = relu(emb@fc1^T + b)@fc2^T + b2
    k_dec<<<gmBlocks, 256, DSM>>>(
        emb, whi + oF1, wlo + oF1, fc1_b,
        whi + oF2, wlo + oF2, fc2_b, recon, NN);
}

// round 15
// speedup vs baseline: 1.1530x; 1.1201x over previous
#include <cuda_runtime.h>
#include <cuda_bf16.h>
#include <cstdint>

#define NN 100000
#define EE 1600000
#define NBLK ((NN + 1023) / 1024)   // 98
#define WTOT 147456                  // total weight elements across 6 matrices

typedef __nv_bfloat16 bf16;

// ---------------- scratch (device globals; no allocation) ----------------
__device__ int      g_is64;
__device__ int      g_deg[NN];
__device__ int      g_off[NN + 1];
__device__ int      g_cursor[NN];
__device__ int      g_bsum[128];
__device__ unsigned g_tick;
__device__ int      g_csr[EE];
__device__ float    g_buf[(size_t)NN * 256];  // mean1 -> pq -> hid (reused)
__device__ float    g_h[(size_t)NN * 256];    // hidden after layer 1
__device__ float    g_bias2[128];             // [0(64) | b_l2(64)]
__device__ bf16     g_whi[WTOT], g_wlo[WTOT];

__device__ __forceinline__ int OFF(int i) { return g_off[i] + g_bsum[i >> 10]; }

// ---------------- prep: split weights + zero + dtype detect ----------------
__global__ void k_prep(const unsigned* ei,
                       const float* Wl1, const float* Wr1,
                       const float* Wl2, const float* Wr2,
                       const float* fc1, const float* fc2,
                       const float* bl2) {
    int i = blockIdx.x * blockDim.x + threadIdx.x;
    if (i == 0) {
        int is64 = 1;
        for (int t = 0; t < 1024; t++)
            if (ei[2 * t + 1] != 0u) { is64 = 0; break; }
        g_is64 = is64;
        g_tick = 0u;
    }
    if (i < NN) { g_deg[i] = 0; g_cursor[i] = 0; }
    if (i < 128) g_bias2[i] = (i < 64) ? 0.f : bl2[i - 64];
    if (i < WTOT) {
        const float* src; int off;
        if      (i < 32768)  { src = Wl1; off = 0; }
        else if (i < 65536)  { src = Wr1; off = 32768; }
        else if (i < 81920)  { src = Wl2; off = 65536; }
        else if (i < 98304)  { src = Wr2; off = 81920; }
        else if (i < 114688) { src = fc1; off = 98304; }
        else                 { src = fc2; off = 114688; }
        float a = src[i - off];
        bf16 h = __float2bfloat16(a);
        g_whi[i] = h;
        g_wlo[i] = __float2bfloat16(a - __bfloat162float(h));
    }
}

__device__ __forceinline__ int eidx(const void* ei, int is64, int idx) {
    if (is64) return (int)((const long long*)ei)[idx];
    return ((const int*)ei)[idx];
}

// 2 edges per thread, vector loads of the dst halves
__global__ void k_hist(const void* ei) {
    int t = blockIdx.x * blockDim.x + threadIdx.x;
    int e = t * 2;
    if (e >= EE) return;
    if (g_is64) {
        longlong2 d = __ldg((const longlong2*)((const long long*)ei + EE) + t);
        atomicAdd(&g_deg[(int)d.x], 1);
        atomicAdd(&g_deg[(int)d.y], 1);
    } else {
        int2 d = __ldg((const int2*)((const int*)ei + EE) + t);
        atomicAdd(&g_deg[d.x], 1);
        atomicAdd(&g_deg[d.y], 1);
    }
}

// ---- fused scan: per-block local scan + decoupled last-block base scan ----
__global__ void k_scan() {
    __shared__ int ws[32];
    __shared__ unsigned last;
    int tid = threadIdx.x, lane = tid & 31, warp = tid >> 5;
    int i = blockIdx.x * 1024 + tid;
    int v = (i < NN) ? g_deg[i] : 0;
    int x = v;
    #pragma unroll
    for (int o = 1; o < 32; o <<= 1) {
        int y = __shfl_up_sync(0xFFFFFFFFu, x, o);
        if (lane >= o) x += y;
    }
    if (lane == 31) ws[warp] = x;
    __syncthreads();
    if (tid < 32) {
        int s = ws[tid];
        #pragma unroll
        for (int o = 1; o < 32; o <<= 1) {
            int y = __shfl_up_sync(0xFFFFFFFFu, s, o);
            if (tid >= o) s += y;
        }
        ws[tid] = s;
    }
    __syncthreads();
    int excl = (warp ? ws[warp - 1] : 0) + (x - v);
    if (i <= NN) g_off[i] = excl;
    if (tid == 0) g_bsum[blockIdx.x] = ws[31];
    __threadfence();
    __syncthreads();
    if (tid == 0) last = (atomicAdd(&g_tick, 1u) == (unsigned)(NBLK - 1)) ? 1u : 0u;
    __syncthreads();
    if (last && tid < 128) {
        int t = tid, ln = t & 31, wp = t >> 5;
        int bv = (t < NBLK) ? *(volatile int*)&g_bsum[t] : 0;
        int bx = bv;
        #pragma unroll
        for (int o = 1; o < 32; o <<= 1) {
            int y = __shfl_up_sync(0xFFFFFFFFu, bx, o);
            if (ln >= o) bx += y;
        }
        if (ln == 31) ws[wp] = bx;
        __syncwarp();
        if (t == 0) { int a = ws[0]; ws[4] = 0; ws[5] = a; ws[6] = a + ws[1]; ws[7] = a + ws[1] + ws[2]; }
        __syncthreads();
        if (t < NBLK) g_bsum[t] = ws[4 + wp] + bx - bv;
    }
}

// 2 edges per thread, vectorized
__global__ void k_scatter(const void* ei) {
    int t = blockIdx.x * blockDim.x + threadIdx.x;
    int e = t * 2;
    if (e >= EE) return;
    if (g_is64) {
        longlong2 s = __ldg((const longlong2*)((const long long*)ei) + t);
        longlong2 d = __ldg((const longlong2*)((const long long*)ei + EE) + t);
        int p0 = atomicAdd(&g_cursor[(int)d.x], 1);
        g_csr[OFF((int)d.x) + p0] = (int)s.x;
        int p1 = atomicAdd(&g_cursor[(int)d.y], 1);
        g_csr[OFF((int)d.y) + p1] = (int)s.y;
    } else {
        int2 s = __ldg((const int2*)((const int*)ei) + t);
        int2 d = __ldg((const int2*)((const int*)ei + EE) + t);
        int p0 = atomicAdd(&g_cursor[d.x], 1);
        g_csr[OFF(d.x) + p0] = s.x;
        int p1 = atomicAdd(&g_cursor[d.y], 1);
        g_csr[OFF(d.y) + p1] = s.y;
    }
}

// ---------------- mean aggregation (F=128): warp/node, 8-way MLP ----------
__global__ void k_agg128(const float* __restrict__ X, float* __restrict__ out) {
    int gw = (blockIdx.x * blockDim.x + threadIdx.x) >> 5;
    int lane = threadIdx.x & 31;
    if (gw >= NN) return;
    int beg = OFF(gw), end = OFF(gw + 1);
    float4 a0 = make_float4(0.f, 0.f, 0.f, 0.f);
    float4 a1 = a0, a2 = a0, a3 = a0, a4 = a0, a5 = a0, a6 = a0, a7 = a0;
    const float4* base = (const float4*)X;
    int e = beg;
    for (; e + 8 <= end; e += 8) {
        int s0 = g_csr[e],     s1 = g_csr[e + 1], s2 = g_csr[e + 2], s3 = g_csr[e + 3];
        int s4 = g_csr[e + 4], s5 = g_csr[e + 5], s6 = g_csr[e + 6], s7 = g_csr[e + 7];
        float4 v0 = __ldg(base + (size_t)s0 * 32 + lane);
        float4 v1 = __ldg(base + (size_t)s1 * 32 + lane);
        float4 v2 = __ldg(base + (size_t)s2 * 32 + lane);
        float4 v3 = __ldg(base + (size_t)s3 * 32 + lane);
        float4 v4 = __ldg(base + (size_t)s4 * 32 + lane);
        float4 v5 = __ldg(base + (size_t)s5 * 32 + lane);
        float4 v6 = __ldg(base + (size_t)s6 * 32 + lane);
        float4 v7 = __ldg(base + (size_t)s7 * 32 + lane);
        a0.x += v0.x; a0.y += v0.y; a0.z += v0.z; a0.w += v0.w;
        a1.x += v1.x; a1.y += v1.y; a1.z += v1.z; a1.w += v1.w;
        a2.x += v2.x; a2.y += v2.y; a2.z += v2.z; a2.w += v2.w;
        a3.x += v3.x; a3.y += v3.y; a3.z += v3.z; a3.w += v3.w;
        a4.x += v4.x; a4.y += v4.y; a4.z += v4.z; a4.w += v4.w;
        a5.x += v5.x; a5.y += v5.y; a5.z += v5.z; a5.w += v5.w;
        a6.x += v6.x; a6.y += v6.y; a6.z += v6.z; a6.w += v6.w;
        a7.x += v7.x; a7.y += v7.y; a7.z += v7.z; a7.w += v7.w;
    }
    for (; e + 4 <= end; e += 4) {
        int s0 = g_csr[e], s1 = g_csr[e + 1], s2 = g_csr[e + 2], s3 = g_csr[e + 3];
        float4 v0 = __ldg(base + (size_t)s0 * 32 + lane);
        float4 v1 = __ldg(base + (size_t)s1 * 32 + lane);
        float4 v2 = __ldg(base + (size_t)s2 * 32 + lane);
        float4 v3 = __ldg(base + (size_t)s3 * 32 + lane);
        a0.x += v0.x; a0.y += v0.y; a0.z += v0.z; a0.w += v0.w;
        a1.x += v1.x; a1.y += v1.y; a1.z += v1.z; a1.w += v1.w;
        a2.x += v2.x; a2.y += v2.y; a2.z += v2.z; a2.w += v2.w;
        a3.x += v3.x; a3.y += v3.y; a3.z += v3.z; a3.w += v3.w;
    }
    for (; e < end; e++) {
        float4 v = __ldg(base + (size_t)g_csr[e] * 32 + lane);
        a0.x += v.x; a0.y += v.y; a0.z += v.z; a0.w += v.w;
    }
    a0.x += a1.x + a2.x + a3.x + a4.x + a5.x + a6.x + a7.x;
    a0.y += a1.y + a2.y + a3.y + a4.y + a5.y + a6.y + a7.y;
    a0.z += a1.z + a2.z + a3.z + a4.z + a5.z + a6.z + a7.z;
    a0.w += a1.w + a2.w + a3.w + a4.w + a5.w + a6.w + a7.w;
    float inv = 1.0f / (float)((end - beg) > 1 ? (end - beg) : 1);
    a0.x *= inv; a0.y *= inv; a0.z *= inv; a0.w *= inv;
    ((float4*)(out + (size_t)gw * 128))[lane] = a0;
}

// ---- layer-2 fused agg: emb[i] = mean_j p[j] + q[i];  pq rows = [p(64)|q(64)]
__global__ void k_agg_add(const float* __restrict__ pq, float* __restrict__ emb) {
    int gw = (blockIdx.x * blockDim.x + threadIdx.x) >> 5;
    int lane = threadIdx.x & 31;
    if (gw >= NN) return;
    int beg = OFF(gw), end = OFF(gw + 1);
    float2 a0 = make_float2(0.f, 0.f);
    float2 a1 = a0, a2 = a0, a3 = a0, a4 = a0, a5 = a0, a6 = a0, a7 = a0;
    const float2* base = (const float2*)pq;
    int e = beg;
    for (; e + 8 <= end; e += 8) {
        int s0 = g_csr[e],     s1 = g_csr[e + 1], s2 = g_csr[e + 2], s3 = g_csr[e + 3];
        int s4 = g_csr[e + 4], s5 = g_csr[e + 5], s6 = g_csr[e + 6], s7 = g_csr[e + 7];
        float2 v0 = __ldg(base + (size_t)s0 * 64 + lane);
        float2 v1 = __ldg(base + (size_t)s1 * 64 + lane);
        float2 v2 = __ldg(base + (size_t)s2 * 64 + lane);
        float2 v3 = __ldg(base + (size_t)s3 * 64 + lane);
        float2 v4 = __ldg(base + (size_t)s4 * 64 + lane);
        float2 v5 = __ldg(base + (size_t)s5 * 64 + lane);
        float2 v6 = __ldg(base + (size_t)s6 * 64 + lane);
        float2 v7 = __ldg(base + (size_t)s7 * 64 + lane);
        a0.x += v0.x; a0.y += v0.y;  a1.x += v1.x; a1.y += v1.y;
        a2.x += v2.x; a2.y += v2.y;  a3.x += v3.x; a3.y += v3.y;
        a4.x += v4.x; a4.y += v4.y;  a5.x += v5.x; a5.y += v5.y;
        a6.x += v6.x; a6.y += v6.y;  a7.x += v7.x; a7.y += v7.y;
    }
    for (; e + 4 <= end; e += 4) {
        int s0 = g_csr[e], s1 = g_csr[e + 1], s2 = g_csr[e + 2], s3 = g_csr[e + 3];
        float2 v0 = __ldg(base + (size_t)s0 * 64 + lane);
        float2 v1 = __ldg(base + (size_t)s1 * 64 + lane);
        float2 v2 = __ldg(base + (size_t)s2 * 64 + lane);
        float2 v3 = __ldg(base + (size_t)s3 * 64 + lane);
        a0.x += v0.x; a0.y += v0.y;  a1.x += v1.x; a1.y += v1.y;
        a2.x += v2.x; a2.y += v2.y;  a3.x += v3.x; a3.y += v3.y;
    }
    for (; e < end; e++) {
        float2 v = __ldg(base + (size_t)g_csr[e] * 64 + lane);
        a0.x += v.x; a0.y += v.y;
    }
    a0.x += a1.x + a2.x + a3.x + a4.x + a5.x + a6.x + a7.x;
    a0.y += a1.y + a2.y + a3.y + a4.y + a5.y + a6.y + a7.y;
    float inv = 1.0f / (float)((end - beg) > 1 ? (end - beg) : 1);
    float2 q = __ldg(base + (size_t)gw * 64 + 32 + lane);
    *(float2*)(emb + (size_t)gw * 64 + lane * 2) =
        make_float2(a0.x * inv + q.x, a0.y * inv + q.y);
}

// ---------------- tensor-core GEMM: bf16 hi/lo split, fp32 accum ----------
__device__ __forceinline__ void mma_bf16(float4& c, const unsigned* a,
                                         unsigned b0, unsigned b1) {
    asm volatile(
        "mma.sync.aligned.m16n8k16.row.col.f32.bf16.bf16.f32 "
        "{%0,%1,%2,%3}, {%4,%5,%6,%7}, {%8,%9}, {%0,%1,%2,%3};"
        : "+f"(c.x), "+f"(c.y), "+f"(c.z), "+f"(c.w)
        : "r"(a[0]), "r"(a[1]), "r"(a[2]), "r"(a[3]), "r"(b0), "r"(b1));
}

__device__ __forceinline__ void ldsm4(unsigned* r, const bf16* p) {
    unsigned addr = (unsigned)__cvta_generic_to_shared(p);
    asm volatile("ldmatrix.sync.aligned.m8n8.x4.shared.b16 {%0,%1,%2,%3}, [%4];"
                 : "=r"(r[0]), "=r"(r[1]), "=r"(r[2]), "=r"(r[3]) : "r"(addr));
}

__device__ __forceinline__ void cpa16(void* dst, const void* src) {
    unsigned d = (unsigned)__cvta_generic_to_shared(dst);
    asm volatile("cp.async.cg.shared.global [%0], [%1], 16;" :: "r"(d), "l"(src));
}

// C[M, NC] = act( A1 @ W1^T + A2 @ W2^T + bias ), W in (hi, lo) bf16.
// BM=128, BK=32, warp tile 64x32, 2xNWN warps. cp.async double-buffered.
template <int BN, int NWN>
__global__ __launch_bounds__(NWN * 64, 2) void k_gemm(
    const float* __restrict__ A1, const bf16* __restrict__ W1h,
    const bf16* __restrict__ W1l, int K1,
    const float* __restrict__ A2, const bf16* __restrict__ W2h,
    const bf16* __restrict__ W2l, int K2,
    const float* __restrict__ bias, float* __restrict__ C,
    int M, int NC, int relu) {
    constexpr int THREADS = NWN * 64;
    constexpr int LDA = 40;
    extern __shared__ __align__(16) char smem[];
    float* stA = (float*)smem;                    // 2 x 4096 fp32 staging
    bf16* Ah = (bf16*)(smem + 32768);             // 128*LDA
    bf16* Al = Ah + 128 * LDA;
    bf16* Bh = Al + 128 * LDA;                    // 2 x BN*LDA
    bf16* Bl = Bh + 2 * BN * LDA;

    int tid = threadIdx.x, lane = tid & 31, w = tid >> 5;
    int g = lane >> 2, tg = lane & 3;
    int lr = lane & 15, lc = (lane >> 4) * 8;
    int brow = ((lane >> 4) << 3) + (lane & 7);     // B ldmatrix row-in-group
    int bk = ((lane >> 3) & 1) << 3;                // B ldmatrix k offset
    int wm0 = (w / NWN) * 64, wn0 = (w % NWN) * 32;
    int row0 = blockIdx.x * 128, col0 = blockIdx.y * BN;

    int t1 = K1 >> 5;
    int T = t1 + ((A2 != nullptr) ? (K2 >> 5) : 0);

    float4 acc[4][4];
    #pragma unroll
    for (int i = 0; i < 4; i++)
        #pragma unroll
        for (int j = 0; j < 4; j++) acc[i][j] = make_float4(0.f, 0.f, 0.f, 0.f);

    auto issue_tile = [&](int t) {
        const float* A; const bf16 *Wh, *Wl; int K, kt;
        if (t < t1) { A = A1; Wh = W1h; Wl = W1l; K = K1; kt = t << 5; }
        else        { A = A2; Wh = W2h; Wl = W2l; K = K2; kt = (t - t1) << 5; }
        float* sa = stA + (t & 1) * 4096;
        #pragma unroll
        for (int c = tid; c < 1024; c += THREADS) {
            int m = c >> 3, kq = c & 7;
            int r = row0 + m; if (r >= M) r = M - 1;
            cpa16(sa + c * 4, A + (size_t)r * K + kt + kq * 4);
        }
        bf16* bh = Bh + (t & 1) * BN * LDA;
        bf16* bl = Bl + (t & 1) * BN * LDA;
        #pragma unroll
        for (int id = tid; id < BN * 4; id += THREADS) {
            int n = id >> 2, kq = id & 3;
            cpa16(&bh[n * LDA + kq * 8], Wh + (size_t)(col0 + n) * K + kt + kq * 8);
            cpa16(&bl[n * LDA + kq * 8], Wl + (size_t)(col0 + n) * K + kt + kq * 8);
        }
        asm volatile("cp.async.commit_group;");
    };

    issue_tile(0);

    for (int t = 0; t < T; t++) {
        asm volatile("cp.async.wait_group 0;");
        __syncthreads();   // publish cp.async data; mma(t-1) done -> Ah/Al reusable
        // split A tile from fp32 staging into bf16 hi/lo planes
        float* sa = stA + (t & 1) * 4096;
        #pragma unroll
        for (int c = tid; c < 1024; c += THREADS) {
            int m = c >> 3, kq = c & 7;
            float4 val = *(const float4*)(sa + c * 4);
            bf16 h0 = __float2bfloat16(val.x), h1 = __float2bfloat16(val.y);
            bf16 h2 = __float2bfloat16(val.z), h3 = __float2bfloat16(val.w);
            *(__nv_bfloat162*)&Ah[m * LDA + kq * 4]     = __halves2bfloat162(h0, h1);
            *(__nv_bfloat162*)&Ah[m * LDA + kq * 4 + 2] = __halves2bfloat162(h2, h3);
            bf16 l0 = __float2bfloat16(val.x - __bfloat162float(h0));
            bf16 l1 = __float2bfloat16(val.y - __bfloat162float(h1));
            bf16 l2 = __float2bfloat16(val.z - __bfloat162float(h2));
            bf16 l3 = __float2bfloat16(val.w - __bfloat162float(h3));
            *(__nv_bfloat162*)&Al[m * LDA + kq * 4]     = __halves2bfloat162(l0, l1);
            *(__nv_bfloat162*)&Al[m * LDA + kq * 4 + 2] = __halves2bfloat162(l2, l3);
        }
        __syncthreads();
        if (t + 1 < T) issue_tile(t + 1);   // loads for t+1 fly under mma(t)
        const bf16* BhT = Bh + (t & 1) * BN * LDA;
        const bf16* BlT = Bl + (t & 1) * BN * LDA;
        #pragma unroll
        for (int ks = 0; ks < 2; ks++) {
            int k0 = ks * 16;
            unsigned Afh[4][4], Afl[4][4];
            unsigned bh01[4], bh23[4], bl01[4], bl23[4];
            #pragma unroll
            for (int mi = 0; mi < 4; mi++) {
                int ro = (wm0 + mi * 16 + lr) * LDA + k0 + lc;
                ldsm4(Afh[mi], &Ah[ro]);
                ldsm4(Afl[mi], &Al[ro]);
            }
            ldsm4(bh01, &BhT[(wn0 + brow) * LDA + k0 + bk]);
            ldsm4(bh23, &BhT[(wn0 + 16 + brow) * LDA + k0 + bk]);
            ldsm4(bl01, &BlT[(wn0 + brow) * LDA + k0 + bk]);
            ldsm4(bl23, &BlT[(wn0 + 16 + brow) * LDA + k0 + bk]);
            #pragma unroll
            for (int mi = 0; mi < 4; mi++) {
                mma_bf16(acc[mi][0], Afh[mi], bh01[0], bh01[1]);
                mma_bf16(acc[mi][0], Afh[mi], bl01[0], bl01[1]);
                mma_bf16(acc[mi][0], Afl[mi], bh01[0], bh01[1]);
                mma_bf16(acc[mi][1], Afh[mi], bh01[2], bh01[3]);
                mma_bf16(acc[mi][1], Afh[mi], bl01[2], bl01[3]);
                mma_bf16(acc[mi][1], Afl[mi], bh01[2], bh01[3]);
                mma_bf16(acc[mi][2], Afh[mi], bh23[0], bh23[1]);
                mma_bf16(acc[mi][2], Afh[mi], bl23[0], bl23[1]);
                mma_bf16(acc[mi][2], Afl[mi], bh23[0], bh23[1]);
                mma_bf16(acc[mi][3], Afh[mi], bh23[2], bh23[3]);
                mma_bf16(acc[mi][3], Afh[mi], bl23[2], bl23[3]);
                mma_bf16(acc[mi][3], Afl[mi], bh23[2], bh23[3]);
            }
        }
    }

    // epilogue
    #pragma unroll
    for (int ni = 0; ni < 4; ni++) {
        int col = col0 + wn0 + ni * 8 + tg * 2;
        float b0 = bias[col], b1 = bias[col + 1];
        #pragma unroll
        for (int mi = 0; mi < 4; mi++) {
            int ra = row0 + wm0 + mi * 16 + g;
            float2 v0 = make_float2(acc[mi][ni].x + b0, acc[mi][ni].y + b1);
            float2 v1 = make_float2(acc[mi][ni].z + b0, acc[mi][ni].w + b1);
            if (relu) {
                v0.x = fmaxf(v0.x, 0.f); v0.y = fmaxf(v0.y, 0.f);
                v1.x = fmaxf(v1.x, 0.f); v1.y = fmaxf(v1.y, 0.f);
            }
            if (ra < M)     *(float2*)(C + (size_t)ra * NC + col) = v0;
            if (ra + 8 < M) *(float2*)(C + (size_t)(ra + 8) * NC + col) = v1;
        }
    }
}

// ---------------- launcher ----------------
extern "C" void kernel_launch(void* const* d_in, const int* in_sizes, int n_in,
                              void* d_out, int out_size) {
    const float* x     = (const float*)d_in[0];
    const void*  ei    = d_in[1];
    const float* W_l1  = (const float*)d_in[2];
    const float* b_l1  = (const float*)d_in[3];
    const float* W_r1  = (const float*)d_in[4];
    const float* W_l2  = (const float*)d_in[5];
    const float* b_l2  = (const float*)d_in[6];
    const float* W_r2  = (const float*)d_in[7];
    const float* fc1_W = (const float*)d_in[8];
    const float* fc1_b = (const float*)d_in[9];
    const float* fc2_W = (const float*)d_in[10];
    const float* fc2_b = (const float*)d_in[11];

    float* emb   = (float*)d_out;                       // [N, 64]
    float* recon = (float*)d_out + (size_t)NN * 64;     // [N, 128]

    float* buf;   cudaGetSymbolAddress((void**)&buf, g_buf);
    float* h;     cudaGetSymbolAddress((void**)&h, g_h);
    float* bias2; cudaGetSymbolAddress((void**)&bias2, g_bias2);
    bf16 *whi, *wlo;
    cudaGetSymbolAddress((void**)&whi, g_whi);
    cudaGetSymbolAddress((void**)&wlo, g_wlo);

    // dynamic smem: staging(32768) + Ah/Al(20480) + Bh/Bl double (40960)
    const int GS = 32768 + 2 * 128 * 40 * 2 + 4 * 128 * 40 * 2;   // 94208
    static int attr_set = 0;
    if (!attr_set) {
        cudaFuncSetAttribute(k_gemm<128, 4>,
                             cudaFuncAttributeMaxDynamicSharedMemorySize, GS);
        attr_set = 1;
    }

    // CSR build + weight split
    k_prep<<<(WTOT + 255) / 256, 256>>>((const unsigned*)ei, W_l1, W_r1, W_l2, W_r2,
                                        fc1_W, fc2_W, b_l2);
    k_hist<<<(EE / 2 + 255) / 256, 256>>>(ei);
    k_scan<<<NBLK, 1024>>>();
    k_scatter<<<(EE / 2 + 255) / 256, 256>>>(ei);

    const int aggBlocks = (NN * 32 + 255) / 256;
    const int gmBlocks  = (NN + 127) / 128;
    const int oWl1 = 0, oWr1 = 32768, oW2 = 65536, oF1 = 98304, oF2 = 114688;

    // Layer 1: h = relu(mean1 @ W_l1^T + x @ W_r1^T + b_l1)
    k_agg128<<<aggBlocks, 256>>>(x, buf);
    k_gemm<128, 4><<<dim3(gmBlocks, 2), 256, GS>>>(
        buf, whi + oWl1, wlo + oWl1, 128,
        x,   whi + oWr1, wlo + oWr1, 128, b_l1, h, NN, 256, 1);

    // Layer 2 (linearity): pq = h @ [W_l2;W_r2]^T + [0|b_l2]; emb = mean(p)+q
    k_gemm<128, 4><<<dim3(gmBlocks, 1), 256, GS>>>(
        h, whi + oW2, wlo + oW2, 256,
        nullptr, nullptr, nullptr, 0, bias2, buf, NN, 128, 0);
    k_agg_add<<<aggBlocks, 256>>>(buf, emb);

    // Decoder: hid = relu(emb @ fc1_W^T + fc1_b);  recon = hid @ fc2_W^T + fc2_b
    k_gemm<128, 4><<<dim3(gmBlocks, 2), 256, GS>>>(
        emb, whi + oF1, wlo + oF1, 64,
        nullptr, nullptr, nullptr, 0, fc1_b, buf, NN, 256, 1);
    k_gemm<128, 4><<<dim3(gmBlocks, 1), 256, GS>>>(
        buf, whi + oF2, wlo + oF2, 256,
        nullptr, nullptr, nullptr, 0, fc2_b, recon, NN, 128, 0);
}